// round 10
// baseline (speedup 1.0000x reference)
#include <cuda_runtime.h>

// ---- transposed quant tables (tabT[v*8+u] = tab[u*8+v]) in global memory ----
__device__ const float g_ytabT[64] = {
 16,12,14,14,18,24,49,72,
 11,12,13,17,22,35,64,92,
 10,14,16,22,37,55,78,95,
 16,19,24,29,56,64,87,98,
 24,26,40,51,68,81,103,112,
 40,58,57,87,109,104,121,100,
 51,60,69,80,103,113,120,103,
 61,55,56,62,77,92,101,99};

// chroma table is symmetric: transpose == itself
__device__ const float g_ctabT[64] = {
 17,18,24,47,99,99,99,99,
 18,21,26,66,99,99,99,99,
 24,26,56,99,99,99,99,99,
 47,66,99,99,99,99,99,99,
 99,99,99,99,99,99,99,99,
 99,99,99,99,99,99,99,99,
 99,99,99,99,99,99,99,99,
 99,99,99,99,99,99,99,99};

// cos(k*pi/16)
#define Kc1 0.980785280403230449f
#define Kc2 0.923879532511286756f
#define Kc3 0.831469612302545237f
#define Kc4 0.707106781186547524f
#define Kc5 0.555570233019602225f
#define Kc6 0.382683432365089772f
#define Kc7 0.195090322016128268f

#define IMG_W 512
#define Y_BLOCKS_PER_IMG 4096
#define C_BLOCKS_PER_IMG 1024

// padded smem geometry: row stride 12 floats, block stride 104 floats
#define RS 12
#define BS 104

// full 8-point DCT-II (even/odd symmetry, 35 ops)
#define DCT8(r0,r1,r2,r3,r4,r5,r6,r7, o0,o1,o2,o3,o4,o5,o6,o7) do {        \
    const float e0=(r0)+(r7), e1=(r1)+(r6), e2=(r2)+(r5), e3=(r3)+(r4);    \
    const float d0=(r0)-(r7), d1=(r1)-(r6), d2=(r2)-(r5), d3=(r3)-(r4);    \
    const float p =e0+e3, q_=e1+e2, ta=e0-e3, tb=e1-e2;                    \
    o0 = p + q_;                                                           \
    o4 = Kc4 * (p - q_);                                                   \
    o2 = fmaf(Kc2, ta,  Kc6 * tb);                                         \
    o6 = fmaf(Kc6, ta, -Kc2 * tb);                                         \
    o1 = fmaf(Kc7, d3, fmaf( Kc5, d2, fmaf( Kc3, d1,  Kc1 * d0)));         \
    o3 = fmaf(-Kc5, d3, fmaf(-Kc1, d2, fmaf(-Kc7, d1,  Kc3 * d0)));        \
    o5 = fmaf( Kc3, d3, fmaf( Kc7, d2, fmaf(-Kc1, d1,  Kc5 * d0)));        \
    o7 = fmaf(-Kc1, d3, fmaf( Kc3, d2, fmaf(-Kc5, d1,  Kc7 * d0)));        \
} while (0)

__global__ __launch_bounds__(256)
void jpeg_fused_kernel(const float* __restrict__ x,
                       const float* __restrict__ fac,
                       float* __restrict__ out,
                       int B)
{
    __shared__ float tmpS[24 * BS];   // Y pass-A transposed (0-15) + chroma (16-23)
    __shared__ float blkC[8 * BS];    // pooled chroma blocks (4 Cb + 4 Cr)

    const int tid = threadIdx.x;
    const int t   = blockIdx.x;
    const int b   = t >> 8;
    const int rem = t & 255;
    const int tr  = rem >> 4;   // 32px tile row (0..15)
    const int tc  = rem & 15;   // 32px tile col (0..15)

    // -------- stage 1: pixel loads (issued first, longest latency) --------
    const int ty  = tid >> 3;   // 0..31  (pixel row in tile)
    const int tx4 = tid & 7;    // 0..7   (group of 4 cols)
    const unsigned plane = IMG_W * IMG_W;
    const float* p = x + (unsigned)(b * 3) * plane
                       + (unsigned)(tr * 32 + ty) * IMG_W + (tc * 32 + tx4 * 4);
    const float4 R  = *(const float4*)p;
    const float4 G  = *(const float4*)(p + plane);
    const float4 Bl = *(const float4*)(p + 2 * plane);

    // -------- hoisted quant scales (overlap MUFU chains with LDG wait) ----
    // identical expression to R5/R8/R9: __fdividef(aav*AU, tab*fv)
    const float fv = __ldg(&fac[b]);
    const int   vq = tid & 7;            // stage-2 column this thread will own
    const float* tabT = (tid < 128) ? g_ytabT : g_ctabT;
    const float4 ta4 = __ldg((const float4*)&tabT[vq * 8]);
    const float4 tb4 = __ldg((const float4*)&tabT[vq * 8 + 4]);
    const float aav = (vq == 0) ? 0.25f * Kc4 : 0.25f;
    float qs[8];
    qs[0] = __fdividef(aav * Kc4,  ta4.x * fv);
    qs[1] = __fdividef(aav * 1.0f, ta4.y * fv);
    qs[2] = __fdividef(aav * 1.0f, ta4.z * fv);
    qs[3] = __fdividef(aav * 1.0f, ta4.w * fv);
    qs[4] = __fdividef(aav * 1.0f, tb4.x * fv);
    qs[5] = __fdividef(aav * 1.0f, tb4.y * fv);
    qs[6] = __fdividef(aav * 1.0f, tb4.z * fv);
    qs[7] = __fdividef(aav * 1.0f, tb4.w * fv);

    // Y*255 - 128 (chroma +128 shift cancels against DCT's -128)
    float4 Yv;
    Yv.x = fmaf(76.245f, R.x, fmaf(149.685f, G.x, fmaf(29.07f, Bl.x, -128.0f)));
    Yv.y = fmaf(76.245f, R.y, fmaf(149.685f, G.y, fmaf(29.07f, Bl.y, -128.0f)));
    Yv.z = fmaf(76.245f, R.z, fmaf(149.685f, G.z, fmaf(29.07f, Bl.z, -128.0f)));
    Yv.w = fmaf(76.245f, R.w, fmaf(149.685f, G.w, fmaf(29.07f, Bl.w, -128.0f)));

    const unsigned FULL = 0xffffffffu;
    float4 Yo;                          // partner half of this 8-px block row
    Yo.x = __shfl_xor_sync(FULL, Yv.x, 1);
    Yo.y = __shfl_xor_sync(FULL, Yv.y, 1);
    Yo.z = __shfl_xor_sync(FULL, Yv.z, 1);
    Yo.w = __shfl_xor_sync(FULL, Yv.w, 1);

    // chroma: horizontal pair sums, transform, then vertical pool (R5 order)
    const float Rs0 = R.x + R.y,   Rs1 = R.z + R.w;
    const float Gs0 = G.x + G.y,   Gs1 = G.z + G.w;
    const float Bs0 = Bl.x + Bl.y, Bs1 = Bl.z + Bl.w;
    const float hb0 = fmaf(-43.02768f, Rs0, fmaf(-84.47232f, Gs0, 127.5f * Bs0));
    const float hb1 = fmaf(-43.02768f, Rs1, fmaf(-84.47232f, Gs1, 127.5f * Bs1));
    const float hr0 = fmaf(127.5f, Rs0, fmaf(-106.76544f, Gs0, -20.73456f * Bs0));
    const float hr1 = fmaf(127.5f, Rs1, fmaf(-106.76544f, Gs1, -20.73456f * Bs1));

    const float ob0 = __shfl_xor_sync(FULL, hb0, 8);
    const float ob1 = __shfl_xor_sync(FULL, hb1, 8);
    const float or0 = __shfl_xor_sync(FULL, hr0, 8);
    const float or1 = __shfl_xor_sync(FULL, hr1, 8);

    if ((ty & 1) == 0) {
        const int pr  = ty >> 1;                       // pooled row 0..15
        const int cbi = ((pr >> 3) << 1) + (tx4 >> 2);
        const int idx = cbi * BS + (pr & 7) * RS + (tx4 & 3) * 2;
        *(float2*)&blkC[idx]          = make_float2(0.25f * (hb0 + ob0),
                                                    0.25f * (hb1 + ob1));
        *(float2*)&blkC[idx + 4 * BS] = make_float2(0.25f * (hr0 + or0),
                                                    0.25f * (hr1 + or1));
    }

    // Y pass A split across the lane pair (bit-identical to full DCT8),
    // stored TRANSPOSED [v][x]; full-warp 4x STS.32, conflict-free
    {
        const int q = ((ty >> 3) << 2) + (tx4 >> 1);   // Y block 0..15
        float* tp = &tmpS[q * BS + (ty & 7)];
        if ((tx4 & 1) == 0) {
            // row = [Yv | Yo]; even-symmetric outputs
            const float e0 = Yv.x + Yo.w, e1 = Yv.y + Yo.z;
            const float e2 = Yv.z + Yo.y, e3 = Yv.w + Yo.x;
            const float pp = e0 + e3, qq = e1 + e2;
            const float ta = e0 - e3, tb = e1 - e2;
            tp[0*RS] = pp + qq;
            tp[4*RS] = Kc4 * (pp - qq);
            tp[2*RS] = fmaf(Kc2, ta,  Kc6 * tb);
            tp[6*RS] = fmaf(Kc6, ta, -Kc2 * tb);
        } else {
            // row = [Yo | Yv]; odd-symmetric outputs
            const float d0 = Yo.x - Yv.w, d1 = Yo.y - Yv.z;
            const float d2 = Yo.z - Yv.y, d3 = Yo.w - Yv.x;
            tp[1*RS] = fmaf(Kc7, d3, fmaf( Kc5, d2, fmaf( Kc3, d1,  Kc1 * d0)));
            tp[3*RS] = fmaf(-Kc5, d3, fmaf(-Kc1, d2, fmaf(-Kc7, d1,  Kc3 * d0)));
            tp[5*RS] = fmaf( Kc3, d3, fmaf( Kc7, d2, fmaf(-Kc1, d1,  Kc5 * d0)));
            tp[7*RS] = fmaf(-Kc1, d3, fmaf( Kc3, d2, fmaf(-Kc5, d1,  Kc7 * d0)));
        }
    }

    __syncthreads();

    // -------- stage 2: pass B + quantize + dense vectorized store --------
    if (tid < 192) {
        int q;
        const int v = vq;            // this lane owns column v of its block
        float4 s0, s1;

        if (tid < 128) {
            q = tid >> 3;
            const float* sp = &tmpS[q * BS + v * RS];
            s0 = *(const float4*)sp;
            s1 = *(const float4*)(sp + 4);
        } else {
            const int cq = (tid - 128) >> 3;            // 0..7
            q = 16 + cq;
            const float* rp = &blkC[cq * BS + v * RS];  // lane = row v for pass A
            const float4 a4 = *(const float4*)rp;
            const float4 b4 = *(const float4*)(rp + 4);
            float t0,t1,t2,t3,t4,t5,t6,t7;
            DCT8(a4.x,a4.y,a4.z,a4.w,b4.x,b4.y,b4.z,b4.w,
                 t0,t1,t2,t3,t4,t5,t6,t7);
            float* tp = &tmpS[q * BS + v];              // v here is row index x
            tp[0*RS]=t0; tp[1*RS]=t1; tp[2*RS]=t2; tp[3*RS]=t3;
            tp[4*RS]=t4; tp[5*RS]=t5; tp[6*RS]=t6; tp[7*RS]=t7;
            __syncwarp();
            const float* sp = &tmpS[q * BS + v * RS];
            s0 = *(const float4*)sp;
            s1 = *(const float4*)(sp + 4);
        }

        // pass B over x (column DCT)
        float o0,o1,o2,o3,o4,o5,o6,o7;
        DCT8(s0.x,s0.y,s0.z,s0.w,s1.x,s1.y,s1.z,s1.w, o0,o1,o2,o3,o4,o5,o6,o7);

        // quantize + diff_round with pre-computed scales
        float res[8];
        #define QZ(U, OV) do {                          \
            const float qt = (OV) * qs[U];              \
            const float rr = rintf(qt);                 \
            const float e  = qt - rr;                   \
            res[U] = fmaf(e * e, e, rr);                \
        } while (0)
        QZ(0, o0); QZ(1, o1); QZ(2, o2); QZ(3, o3);
        QZ(4, o4); QZ(5, o5); QZ(6, o6); QZ(7, o7);
        #undef QZ

        __syncwarp();                       // octet done reading its slot rows
        // DENSE transpose: res[u] -> slot[u*8 + v]  (banks 8(q+u)+v: no conflict)
        float* dp = &tmpS[q * BS];
        dp[0*8+v]=res[0]; dp[1*8+v]=res[1]; dp[2*8+v]=res[2]; dp[3*8+v]=res[3];
        dp[4*8+v]=res[4]; dp[5*8+v]=res[5]; dp[6*8+v]=res[6]; dp[7*8+v]=res[7];
        __syncwarp();

        // lane v emits dense quarters: each STG.128 = contiguous 128B per octet
        const float4 w0 = *(const float4*)&dp[4 * v];
        const float4 w1 = *(const float4*)&dp[32 + 4 * v];

        unsigned base;   // element offset, fits in 32 bits (<13M)
        if (q < 16) {
            const int h8 = tr * 4 + (q >> 2);
            const int w8 = tc * 4 + (q & 3);
            base = (unsigned)b * (Y_BLOCKS_PER_IMG * 64)
                 + (unsigned)(h8 * 64 + w8) * 64;
        } else {
            const int cq  = (q - 16) & 3;
            const int ch8 = tr * 2 + (cq >> 1);
            const int cw8 = tc * 2 + (cq & 1);
            base = (unsigned)B * (Y_BLOCKS_PER_IMG * 64)
                 + ((q >= 20) ? (unsigned)B * (C_BLOCKS_PER_IMG * 64) : 0u)
                 + (unsigned)b * (C_BLOCKS_PER_IMG * 64)
                 + (unsigned)(ch8 * 32 + cw8) * 64;
        }
        float* dst = &out[base];
        *(float4*)&dst[4 * v]      = w0;
        *(float4*)&dst[32 + 4 * v] = w1;
    }
}

extern "C" void kernel_launch(void* const* d_in, const int* in_sizes, int n_in,
                              void* d_out, int out_size)
{
    const float* x   = (const float*)d_in[0];   // [B,3,512,512]
    const float* fac = (const float*)d_in[1];   // [B]
    float* out = (float*)d_out;

    const int B = in_sizes[1];
    const int grid = B * 256;        // one CTA per 32x32 pixel tile
    jpeg_fused_kernel<<<grid, 256>>>(x, fac, out, B);
}

// round 11
// speedup vs baseline: 1.0559x; 1.0559x over previous
#include <cuda_runtime.h>

// ---- transposed quant tables (tabT[v*8+u] = tab[u*8+v]) in global memory ----
__device__ const float g_ytabT[64] = {
 16,12,14,14,18,24,49,72,
 11,12,13,17,22,35,64,92,
 10,14,16,22,37,55,78,95,
 16,19,24,29,56,64,87,98,
 24,26,40,51,68,81,103,112,
 40,58,57,87,109,104,121,100,
 51,60,69,80,103,113,120,103,
 61,55,56,62,77,92,101,99};

// chroma table is symmetric: transpose == itself
__device__ const float g_ctabT[64] = {
 17,18,24,47,99,99,99,99,
 18,21,26,66,99,99,99,99,
 24,26,56,99,99,99,99,99,
 47,66,99,99,99,99,99,99,
 99,99,99,99,99,99,99,99,
 99,99,99,99,99,99,99,99,
 99,99,99,99,99,99,99,99,
 99,99,99,99,99,99,99,99};

// cos(k*pi/16)
#define Kc1 0.980785280403230449f
#define Kc2 0.923879532511286756f
#define Kc3 0.831469612302545237f
#define Kc4 0.707106781186547524f
#define Kc5 0.555570233019602225f
#define Kc6 0.382683432365089772f
#define Kc7 0.195090322016128268f

#define IMG_W 512
#define Y_BLOCKS_PER_IMG 4096
#define C_BLOCKS_PER_IMG 1024

// padded smem geometry: row stride 12 floats, block stride 104 floats
#define RS 12
#define BS 104

// full 8-point DCT-II (even/odd symmetry, 35 ops)
#define DCT8(r0,r1,r2,r3,r4,r5,r6,r7, o0,o1,o2,o3,o4,o5,o6,o7) do {        \
    const float e0=(r0)+(r7), e1=(r1)+(r6), e2=(r2)+(r5), e3=(r3)+(r4);    \
    const float d0=(r0)-(r7), d1=(r1)-(r6), d2=(r2)-(r5), d3=(r3)-(r4);    \
    const float p =e0+e3, q_=e1+e2, ta=e0-e3, tb=e1-e2;                    \
    o0 = p + q_;                                                           \
    o4 = Kc4 * (p - q_);                                                   \
    o2 = fmaf(Kc2, ta,  Kc6 * tb);                                         \
    o6 = fmaf(Kc6, ta, -Kc2 * tb);                                         \
    o1 = fmaf(Kc7, d3, fmaf( Kc5, d2, fmaf( Kc3, d1,  Kc1 * d0)));         \
    o3 = fmaf(-Kc5, d3, fmaf(-Kc1, d2, fmaf(-Kc7, d1,  Kc3 * d0)));        \
    o5 = fmaf( Kc3, d3, fmaf( Kc7, d2, fmaf(-Kc1, d1,  Kc5 * d0)));        \
    o7 = fmaf(-Kc1, d3, fmaf( Kc3, d2, fmaf(-Kc5, d1,  Kc7 * d0)));        \
} while (0)

// quantize + diff_round; qs formula identical to R5/R8/R9 (verified rel_err)
#define QZ(RES, OV, TT, AU) do {                                 \
    const float qs = __fdividef(aav * (AU), (TT) * fv);          \
    const float qt = (OV) * qs;                                  \
    const float rr = rintf(qt);                                  \
    const float e  = qt - rr;                                    \
    RES = fmaf(e * e, e, rr);                                    \
} while (0)

__global__ __launch_bounds__(256)
void jpeg_fused_kernel(const float* __restrict__ x,
                       const float* __restrict__ fac,
                       float* __restrict__ out,
                       int B)
{
    __shared__ float tmpS[24 * BS];   // Y pass-A transposed (0-15) + chroma (16-23)
    __shared__ float blkC[8 * BS];    // pooled chroma blocks (4 Cb + 4 Cr)

    const int tid = threadIdx.x;
    const int t   = blockIdx.x;
    const int b   = t >> 8;
    const int rem = t & 255;
    const int tr  = rem >> 4;   // 32px tile row (0..15)
    const int tc  = rem & 15;   // 32px tile col (0..15)

    // -------- stage 1 (R5/R9 arithmetic) --------
    const int ty  = tid >> 3;   // 0..31  (pixel row in tile)
    const int tx4 = tid & 7;    // 0..7   (group of 4 cols)
    const unsigned plane = IMG_W * IMG_W;
    const float* p = x + (unsigned)(b * 3) * plane
                       + (unsigned)(tr * 32 + ty) * IMG_W + (tc * 32 + tx4 * 4);
    const float4 R  = *(const float4*)p;
    const float4 G  = *(const float4*)(p + plane);
    const float4 Bl = *(const float4*)(p + 2 * plane);

    const float fv = __ldg(&fac[b]);

    // Y*255 - 128 (chroma +128 shift cancels against DCT's -128)
    float4 Yv;
    Yv.x = fmaf(76.245f, R.x, fmaf(149.685f, G.x, fmaf(29.07f, Bl.x, -128.0f)));
    Yv.y = fmaf(76.245f, R.y, fmaf(149.685f, G.y, fmaf(29.07f, Bl.y, -128.0f)));
    Yv.z = fmaf(76.245f, R.z, fmaf(149.685f, G.z, fmaf(29.07f, Bl.z, -128.0f)));
    Yv.w = fmaf(76.245f, R.w, fmaf(149.685f, G.w, fmaf(29.07f, Bl.w, -128.0f)));

    const unsigned FULL = 0xffffffffu;
    float4 Yo;                          // partner half of this 8-px block row
    Yo.x = __shfl_xor_sync(FULL, Yv.x, 1);
    Yo.y = __shfl_xor_sync(FULL, Yv.y, 1);
    Yo.z = __shfl_xor_sync(FULL, Yv.z, 1);
    Yo.w = __shfl_xor_sync(FULL, Yv.w, 1);

    // chroma: horizontal pair sums, transform, then vertical pool (R5 order)
    const float Rs0 = R.x + R.y,   Rs1 = R.z + R.w;
    const float Gs0 = G.x + G.y,   Gs1 = G.z + G.w;
    const float Bs0 = Bl.x + Bl.y, Bs1 = Bl.z + Bl.w;
    const float hb0 = fmaf(-43.02768f, Rs0, fmaf(-84.47232f, Gs0, 127.5f * Bs0));
    const float hb1 = fmaf(-43.02768f, Rs1, fmaf(-84.47232f, Gs1, 127.5f * Bs1));
    const float hr0 = fmaf(127.5f, Rs0, fmaf(-106.76544f, Gs0, -20.73456f * Bs0));
    const float hr1 = fmaf(127.5f, Rs1, fmaf(-106.76544f, Gs1, -20.73456f * Bs1));

    const float ob0 = __shfl_xor_sync(FULL, hb0, 8);
    const float ob1 = __shfl_xor_sync(FULL, hb1, 8);
    const float or0 = __shfl_xor_sync(FULL, hr0, 8);
    const float or1 = __shfl_xor_sync(FULL, hr1, 8);

    if ((ty & 1) == 0) {
        const int pr  = ty >> 1;                       // pooled row 0..15
        const int cbi = ((pr >> 3) << 1) + (tx4 >> 2);
        const int idx = cbi * BS + (pr & 7) * RS + (tx4 & 3) * 2;
        *(float2*)&blkC[idx]          = make_float2(0.25f * (hb0 + ob0),
                                                    0.25f * (hb1 + ob1));
        *(float2*)&blkC[idx + 4 * BS] = make_float2(0.25f * (hr0 + or0),
                                                    0.25f * (hr1 + or1));
    }

    // Y pass A split across the lane pair (bit-identical to full DCT8),
    // stored TRANSPOSED [v][x]; full-warp 4x STS.32, conflict-free
    {
        const int q = ((ty >> 3) << 2) + (tx4 >> 1);   // Y block 0..15
        float* tp = &tmpS[q * BS + (ty & 7)];
        if ((tx4 & 1) == 0) {
            // row = [Yv | Yo]; even-symmetric outputs
            const float e0 = Yv.x + Yo.w, e1 = Yv.y + Yo.z;
            const float e2 = Yv.z + Yo.y, e3 = Yv.w + Yo.x;
            const float pp = e0 + e3, qq = e1 + e2;
            const float ta = e0 - e3, tb = e1 - e2;
            tp[0*RS] = pp + qq;
            tp[4*RS] = Kc4 * (pp - qq);
            tp[2*RS] = fmaf(Kc2, ta,  Kc6 * tb);
            tp[6*RS] = fmaf(Kc6, ta, -Kc2 * tb);
        } else {
            // row = [Yo | Yv]; odd-symmetric outputs
            const float d0 = Yo.x - Yv.w, d1 = Yo.y - Yv.z;
            const float d2 = Yo.z - Yv.y, d3 = Yo.w - Yv.x;
            tp[1*RS] = fmaf(Kc7, d3, fmaf( Kc5, d2, fmaf( Kc3, d1,  Kc1 * d0)));
            tp[3*RS] = fmaf(-Kc5, d3, fmaf(-Kc1, d2, fmaf(-Kc7, d1,  Kc3 * d0)));
            tp[5*RS] = fmaf( Kc3, d3, fmaf( Kc7, d2, fmaf(-Kc1, d1,  Kc5 * d0)));
            tp[7*RS] = fmaf(-Kc1, d3, fmaf( Kc3, d2, fmaf(-Kc5, d1,  Kc7 * d0)));
        }
    }

    __syncthreads();

    // -------- stage 2: pass B + quantize + DENSE vectorized store --------
    if (tid < 192) {
        int q;
        const int v = tid & 7;       // this lane owns column v of its block
        float4 s0, s1;

        if (tid < 128) {
            q = tid >> 3;
            const float* sp = &tmpS[q * BS + v * RS];
            s0 = *(const float4*)sp;
            s1 = *(const float4*)(sp + 4);
        } else {
            const int cq = (tid - 128) >> 3;            // 0..7
            q = 16 + cq;
            const float* rp = &blkC[cq * BS + v * RS];  // lane = row v for pass A
            const float4 a4 = *(const float4*)rp;
            const float4 b4 = *(const float4*)(rp + 4);
            float t0,t1,t2,t3,t4,t5,t6,t7;
            DCT8(a4.x,a4.y,a4.z,a4.w,b4.x,b4.y,b4.z,b4.w,
                 t0,t1,t2,t3,t4,t5,t6,t7);
            float* tp = &tmpS[q * BS + v];              // v here is row index x
            tp[0*RS]=t0; tp[1*RS]=t1; tp[2*RS]=t2; tp[3*RS]=t3;
            tp[4*RS]=t4; tp[5*RS]=t5; tp[6*RS]=t6; tp[7*RS]=t7;
            __syncwarp();
            const float* sp = &tmpS[q * BS + v * RS];
            s0 = *(const float4*)sp;
            s1 = *(const float4*)(sp + 4);
        }

        // pass B over x (column DCT)
        float o0,o1,o2,o3,o4,o5,o6,o7;
        DCT8(s0.x,s0.y,s0.z,s0.w,s1.x,s1.y,s1.z,s1.w, o0,o1,o2,o3,o4,o5,o6,o7);

        // per-lane quant scales (R9 placement: post-barrier, no live state)
        const float* tabT = (q < 16) ? g_ytabT : g_ctabT;
        const float4 ta4 = __ldg((const float4*)&tabT[v * 8]);
        const float4 tb4 = __ldg((const float4*)&tabT[v * 8 + 4]);
        const float aav = (v == 0) ? 0.25f * Kc4 : 0.25f;

        float res[8];
        QZ(res[0], o0, ta4.x, Kc4); QZ(res[1], o1, ta4.y, 1.0f);
        QZ(res[2], o2, ta4.z, 1.0f); QZ(res[3], o3, ta4.w, 1.0f);
        QZ(res[4], o4, tb4.x, 1.0f); QZ(res[5], o5, tb4.y, 1.0f);
        QZ(res[6], o6, tb4.z, 1.0f); QZ(res[7], o7, tb4.w, 1.0f);

        __syncwarp();                       // octet done reading its slot rows
        // DENSE transpose: res[u] -> slot[u*8+v]  (banks 8(q+u)+v: conflict-free)
        float* dp = &tmpS[q * BS];
        dp[0*8+v]=res[0]; dp[1*8+v]=res[1]; dp[2*8+v]=res[2]; dp[3*8+v]=res[3];
        dp[4*8+v]=res[4]; dp[5*8+v]=res[5]; dp[6*8+v]=res[6]; dp[7*8+v]=res[7];
        __syncwarp();

        // lane v emits dense quarters: each STG.128 = contiguous 128B per octet
        const float4 w0 = *(const float4*)&dp[4 * v];
        const float4 w1 = *(const float4*)&dp[32 + 4 * v];

        unsigned base;   // element offset, fits in 32 bits (<13M)
        if (q < 16) {
            const int h8 = tr * 4 + (q >> 2);
            const int w8 = tc * 4 + (q & 3);
            base = (unsigned)b * (Y_BLOCKS_PER_IMG * 64)
                 + (unsigned)(h8 * 64 + w8) * 64;
        } else {
            const int cq  = (q - 16) & 3;
            const int ch8 = tr * 2 + (cq >> 1);
            const int cw8 = tc * 2 + (cq & 1);
            base = (unsigned)B * (Y_BLOCKS_PER_IMG * 64)
                 + ((q >= 20) ? (unsigned)B * (C_BLOCKS_PER_IMG * 64) : 0u)
                 + (unsigned)b * (C_BLOCKS_PER_IMG * 64)
                 + (unsigned)(ch8 * 32 + cw8) * 64;
        }
        float* dst = &out[base];
        *(float4*)&dst[4 * v]      = w0;
        *(float4*)&dst[32 + 4 * v] = w1;
    }
}

extern "C" void kernel_launch(void* const* d_in, const int* in_sizes, int n_in,
                              void* d_out, int out_size)
{
    const float* x   = (const float*)d_in[0];   // [B,3,512,512]
    const float* fac = (const float*)d_in[1];   // [B]
    float* out = (float*)d_out;

    const int B = in_sizes[1];
    const int grid = B * 256;        // one CTA per 32x32 pixel tile
    jpeg_fused_kernel<<<grid, 256>>>(x, fac, out, B);
}

// round 12
// speedup vs baseline: 1.1393x; 1.0789x over previous
#include <cuda_runtime.h>

// ---- transposed quant tables (tabT[v*8+u] = tab[u*8+v]) in global memory ----
__device__ const float g_ytabT[64] = {
 16,12,14,14,18,24,49,72,
 11,12,13,17,22,35,64,92,
 10,14,16,22,37,55,78,95,
 16,19,24,29,56,64,87,98,
 24,26,40,51,68,81,103,112,
 40,58,57,87,109,104,121,100,
 51,60,69,80,103,113,120,103,
 61,55,56,62,77,92,101,99};

// chroma table is symmetric: transpose == itself
__device__ const float g_ctabT[64] = {
 17,18,24,47,99,99,99,99,
 18,21,26,66,99,99,99,99,
 24,26,56,99,99,99,99,99,
 47,66,99,99,99,99,99,99,
 99,99,99,99,99,99,99,99,
 99,99,99,99,99,99,99,99,
 99,99,99,99,99,99,99,99,
 99,99,99,99,99,99,99,99};

// cos(k*pi/16)
#define Kc1 0.980785280403230449f
#define Kc2 0.923879532511286756f
#define Kc3 0.831469612302545237f
#define Kc4 0.707106781186547524f
#define Kc5 0.555570233019602225f
#define Kc6 0.382683432365089772f
#define Kc7 0.195090322016128268f

#define IMG_W 512
#define Y_BLOCKS_PER_IMG 4096
#define C_BLOCKS_PER_IMG 1024

// padded smem geometry: row stride 12 floats, block stride 104 floats
#define RS 12
#define BS 104

// full 8-point DCT-II (even/odd symmetry, 35 ops)
#define DCT8(r0,r1,r2,r3,r4,r5,r6,r7, o0,o1,o2,o3,o4,o5,o6,o7) do {        \
    const float e0=(r0)+(r7), e1=(r1)+(r6), e2=(r2)+(r5), e3=(r3)+(r4);    \
    const float d0=(r0)-(r7), d1=(r1)-(r6), d2=(r2)-(r5), d3=(r3)-(r4);    \
    const float p =e0+e3, q_=e1+e2, ta=e0-e3, tb=e1-e2;                    \
    o0 = p + q_;                                                           \
    o4 = Kc4 * (p - q_);                                                   \
    o2 = fmaf(Kc2, ta,  Kc6 * tb);                                         \
    o6 = fmaf(Kc6, ta, -Kc2 * tb);                                         \
    o1 = fmaf(Kc7, d3, fmaf( Kc5, d2, fmaf( Kc3, d1,  Kc1 * d0)));         \
    o3 = fmaf(-Kc5, d3, fmaf(-Kc1, d2, fmaf(-Kc7, d1,  Kc3 * d0)));        \
    o5 = fmaf( Kc3, d3, fmaf( Kc7, d2, fmaf(-Kc1, d1,  Kc5 * d0)));        \
    o7 = fmaf(-Kc1, d3, fmaf( Kc3, d2, fmaf(-Kc5, d1,  Kc7 * d0)));        \
} while (0)

// quantize + diff_round; qs formula identical to R5/R8/R9 (verified rel_err)
#define QZ(RES, OV, TT, AU) do {                                 \
    const float qs = __fdividef(aav * (AU), (TT) * fv);          \
    const float qt = (OV) * qs;                                  \
    const float rr = rintf(qt);                                  \
    const float e  = qt - rr;                                    \
    RES = fmaf(e * e, e, rr);                                    \
} while (0)

__global__ __launch_bounds__(256)
void jpeg_fused_kernel(const float* __restrict__ x,
                       const float* __restrict__ fac,
                       float* __restrict__ out,
                       int B)
{
    __shared__ float tmpS[24 * BS];   // Y pass-A transposed (0-15) + chroma (16-23)
    __shared__ float blkC[8 * BS];    // pooled chroma blocks (4 Cb + 4 Cr)

    const int tid = threadIdx.x;
    const int t   = blockIdx.x;
    const int b   = t >> 8;
    const int rem = t & 255;
    const int tr  = rem >> 4;   // 32px tile row (0..15)
    const int tc  = rem & 15;   // 32px tile col (0..15)

    // -------- stage 1 (R5/R9 arithmetic); streaming loads (read-once) ------
    const int ty  = tid >> 3;   // 0..31  (pixel row in tile)
    const int tx4 = tid & 7;    // 0..7   (group of 4 cols)
    const unsigned plane = IMG_W * IMG_W;
    const float* p = x + (unsigned)(b * 3) * plane
                       + (unsigned)(tr * 32 + ty) * IMG_W + (tc * 32 + tx4 * 4);
    const float4 R  = __ldcs((const float4*)p);
    const float4 G  = __ldcs((const float4*)(p + plane));
    const float4 Bl = __ldcs((const float4*)(p + 2 * plane));

    const float fv = __ldg(&fac[b]);   // reused across CTAs: keep cached

    // Y*255 - 128 (chroma +128 shift cancels against DCT's -128)
    float4 Yv;
    Yv.x = fmaf(76.245f, R.x, fmaf(149.685f, G.x, fmaf(29.07f, Bl.x, -128.0f)));
    Yv.y = fmaf(76.245f, R.y, fmaf(149.685f, G.y, fmaf(29.07f, Bl.y, -128.0f)));
    Yv.z = fmaf(76.245f, R.z, fmaf(149.685f, G.z, fmaf(29.07f, Bl.z, -128.0f)));
    Yv.w = fmaf(76.245f, R.w, fmaf(149.685f, G.w, fmaf(29.07f, Bl.w, -128.0f)));

    const unsigned FULL = 0xffffffffu;
    float4 Yo;                          // partner half of this 8-px block row
    Yo.x = __shfl_xor_sync(FULL, Yv.x, 1);
    Yo.y = __shfl_xor_sync(FULL, Yv.y, 1);
    Yo.z = __shfl_xor_sync(FULL, Yv.z, 1);
    Yo.w = __shfl_xor_sync(FULL, Yv.w, 1);

    // chroma: horizontal pair sums, transform, then vertical pool (R5 order)
    const float Rs0 = R.x + R.y,   Rs1 = R.z + R.w;
    const float Gs0 = G.x + G.y,   Gs1 = G.z + G.w;
    const float Bs0 = Bl.x + Bl.y, Bs1 = Bl.z + Bl.w;
    const float hb0 = fmaf(-43.02768f, Rs0, fmaf(-84.47232f, Gs0, 127.5f * Bs0));
    const float hb1 = fmaf(-43.02768f, Rs1, fmaf(-84.47232f, Gs1, 127.5f * Bs1));
    const float hr0 = fmaf(127.5f, Rs0, fmaf(-106.76544f, Gs0, -20.73456f * Bs0));
    const float hr1 = fmaf(127.5f, Rs1, fmaf(-106.76544f, Gs1, -20.73456f * Bs1));

    const float ob0 = __shfl_xor_sync(FULL, hb0, 8);
    const float ob1 = __shfl_xor_sync(FULL, hb1, 8);
    const float or0 = __shfl_xor_sync(FULL, hr0, 8);
    const float or1 = __shfl_xor_sync(FULL, hr1, 8);

    if ((ty & 1) == 0) {
        const int pr  = ty >> 1;                       // pooled row 0..15
        const int cbi = ((pr >> 3) << 1) + (tx4 >> 2);
        const int idx = cbi * BS + (pr & 7) * RS + (tx4 & 3) * 2;
        *(float2*)&blkC[idx]          = make_float2(0.25f * (hb0 + ob0),
                                                    0.25f * (hb1 + ob1));
        *(float2*)&blkC[idx + 4 * BS] = make_float2(0.25f * (hr0 + or0),
                                                    0.25f * (hr1 + or1));
    }

    // Y pass A split across the lane pair (bit-identical to full DCT8),
    // stored TRANSPOSED [v][x]; full-warp 4x STS.32, conflict-free
    {
        const int q = ((ty >> 3) << 2) + (tx4 >> 1);   // Y block 0..15
        float* tp = &tmpS[q * BS + (ty & 7)];
        if ((tx4 & 1) == 0) {
            // row = [Yv | Yo]; even-symmetric outputs
            const float e0 = Yv.x + Yo.w, e1 = Yv.y + Yo.z;
            const float e2 = Yv.z + Yo.y, e3 = Yv.w + Yo.x;
            const float pp = e0 + e3, qq = e1 + e2;
            const float ta = e0 - e3, tb = e1 - e2;
            tp[0*RS] = pp + qq;
            tp[4*RS] = Kc4 * (pp - qq);
            tp[2*RS] = fmaf(Kc2, ta,  Kc6 * tb);
            tp[6*RS] = fmaf(Kc6, ta, -Kc2 * tb);
        } else {
            // row = [Yo | Yv]; odd-symmetric outputs
            const float d0 = Yo.x - Yv.w, d1 = Yo.y - Yv.z;
            const float d2 = Yo.z - Yv.y, d3 = Yo.w - Yv.x;
            tp[1*RS] = fmaf(Kc7, d3, fmaf( Kc5, d2, fmaf( Kc3, d1,  Kc1 * d0)));
            tp[3*RS] = fmaf(-Kc5, d3, fmaf(-Kc1, d2, fmaf(-Kc7, d1,  Kc3 * d0)));
            tp[5*RS] = fmaf( Kc3, d3, fmaf( Kc7, d2, fmaf(-Kc1, d1,  Kc5 * d0)));
            tp[7*RS] = fmaf(-Kc1, d3, fmaf( Kc3, d2, fmaf(-Kc5, d1,  Kc7 * d0)));
        }
    }

    __syncthreads();

    // -------- stage 2: pass B + quantize + DENSE vectorized store --------
    if (tid < 192) {
        int q;
        const int v = tid & 7;       // this lane owns column v of its block
        float4 s0, s1;

        if (tid < 128) {
            q = tid >> 3;
            const float* sp = &tmpS[q * BS + v * RS];
            s0 = *(const float4*)sp;
            s1 = *(const float4*)(sp + 4);
        } else {
            const int cq = (tid - 128) >> 3;            // 0..7
            q = 16 + cq;
            const float* rp = &blkC[cq * BS + v * RS];  // lane = row v for pass A
            const float4 a4 = *(const float4*)rp;
            const float4 b4 = *(const float4*)(rp + 4);
            float t0,t1,t2,t3,t4,t5,t6,t7;
            DCT8(a4.x,a4.y,a4.z,a4.w,b4.x,b4.y,b4.z,b4.w,
                 t0,t1,t2,t3,t4,t5,t6,t7);
            float* tp = &tmpS[q * BS + v];              // v here is row index x
            tp[0*RS]=t0; tp[1*RS]=t1; tp[2*RS]=t2; tp[3*RS]=t3;
            tp[4*RS]=t4; tp[5*RS]=t5; tp[6*RS]=t6; tp[7*RS]=t7;
            __syncwarp();
            const float* sp = &tmpS[q * BS + v * RS];
            s0 = *(const float4*)sp;
            s1 = *(const float4*)(sp + 4);
        }

        // pass B over x (column DCT)
        float o0,o1,o2,o3,o4,o5,o6,o7;
        DCT8(s0.x,s0.y,s0.z,s0.w,s1.x,s1.y,s1.z,s1.w, o0,o1,o2,o3,o4,o5,o6,o7);

        // per-lane quant scales (R9 placement: post-barrier, no live state)
        const float* tabT = (q < 16) ? g_ytabT : g_ctabT;
        const float4 ta4 = __ldg((const float4*)&tabT[v * 8]);
        const float4 tb4 = __ldg((const float4*)&tabT[v * 8 + 4]);
        const float aav = (v == 0) ? 0.25f * Kc4 : 0.25f;

        float res[8];
        QZ(res[0], o0, ta4.x, Kc4); QZ(res[1], o1, ta4.y, 1.0f);
        QZ(res[2], o2, ta4.z, 1.0f); QZ(res[3], o3, ta4.w, 1.0f);
        QZ(res[4], o4, tb4.x, 1.0f); QZ(res[5], o5, tb4.y, 1.0f);
        QZ(res[6], o6, tb4.z, 1.0f); QZ(res[7], o7, tb4.w, 1.0f);

        __syncwarp();                       // octet done reading its slot rows
        // DENSE transpose: res[u] -> slot[u*8+v]  (banks 8(q+u)+v: conflict-free)
        float* dp = &tmpS[q * BS];
        dp[0*8+v]=res[0]; dp[1*8+v]=res[1]; dp[2*8+v]=res[2]; dp[3*8+v]=res[3];
        dp[4*8+v]=res[4]; dp[5*8+v]=res[5]; dp[6*8+v]=res[6]; dp[7*8+v]=res[7];
        __syncwarp();

        // lane v emits dense quarters: each STG.128 = contiguous 128B per octet
        const float4 w0 = *(const float4*)&dp[4 * v];
        const float4 w1 = *(const float4*)&dp[32 + 4 * v];

        unsigned base;   // element offset, fits in 32 bits (<13M)
        if (q < 16) {
            const int h8 = tr * 4 + (q >> 2);
            const int w8 = tc * 4 + (q & 3);
            base = (unsigned)b * (Y_BLOCKS_PER_IMG * 64)
                 + (unsigned)(h8 * 64 + w8) * 64;
        } else {
            const int cq  = (q - 16) & 3;
            const int ch8 = tr * 2 + (cq >> 1);
            const int cw8 = tc * 2 + (cq & 1);
            base = (unsigned)B * (Y_BLOCKS_PER_IMG * 64)
                 + ((q >= 20) ? (unsigned)B * (C_BLOCKS_PER_IMG * 64) : 0u)
                 + (unsigned)b * (C_BLOCKS_PER_IMG * 64)
                 + (unsigned)(ch8 * 32 + cw8) * 64;
        }
        float* dst = &out[base];
        __stcs((float4*)&dst[4 * v],      w0);   // write-once: stream past L2
        __stcs((float4*)&dst[32 + 4 * v], w1);
    }
}

extern "C" void kernel_launch(void* const* d_in, const int* in_sizes, int n_in,
                              void* d_out, int out_size)
{
    const float* x   = (const float*)d_in[0];   // [B,3,512,512]
    const float* fac = (const float*)d_in[1];   // [B]
    float* out = (float*)d_out;

    const int B = in_sizes[1];
    const int grid = B * 256;        // one CTA per 32x32 pixel tile
    jpeg_fused_kernel<<<grid, 256>>>(x, fac, out, B);
}